// round 1
// baseline (speedup 1.0000x reference)
#include <cuda_runtime.h>
#include <cstdint>

#define B_TOT   32768
#define T_LEN   40
#define F_DIM   92
#define H_DIM   64
#define G_DIM   256      // 4*H
#define ROWS    32       // batch rows per block
#define THREADS 256
#define NL      2

typedef unsigned long long ull;

// ---- shared layout (float offsets) ----
#define OFF_WK  0                         // [92][256]
#define OFF_WR  (OFF_WK + F_DIM*G_DIM)    // [64][256]
#define OFF_B   (OFF_WR + H_DIM*G_DIM)    // [256]
#define OFF_WD  (OFF_B  + G_DIM)          // [64][2]
#define OFF_X   (OFF_WD + H_DIM*NL)       // [32][92]   (16B aligned: 40320*4)
#define OFF_H   (OFF_X  + ROWS*F_DIM)     // [32][64]
#define SMEM_FLOATS (OFF_H + ROWS*H_DIM)
#define SMEM_BYTES  (SMEM_FLOATS * 4)

__device__ __forceinline__ void fma2(ull &acc, ull a, ull w) {
    asm("fma.rn.f32x2 %0, %1, %2, %0;" : "+l"(acc) : "l"(a), "l"(w));
}
__device__ __forceinline__ ull pack2(float v) {
    ull r; asm("mov.b64 %0, {%1,%2};" : "=l"(r) : "f"(v), "f"(v)); return r;
}
__device__ __forceinline__ float2 unpack2(ull v) {
    float2 r; asm("mov.b64 {%0,%1}, %2;" : "=f"(r.x), "=f"(r.y) : "l"(v)); return r;
}

__device__ __forceinline__ float sig_acc(float x) {
    return 1.0f / (1.0f + __expf(-x));
}
__device__ __forceinline__ float tanh_acc(float x) {
    float a = fabsf(x);
    float e = __expf(-2.0f * a);        // in (0,1], no overflow
    float t = (1.0f - e) / (1.0f + e);
    return copysignf(t, x);
}

__global__ void __launch_bounds__(THREADS, 1)
lstm_persist_kernel(const float* __restrict__ x,
                    const float* __restrict__ Wk,
                    const float* __restrict__ Wr,
                    const float* __restrict__ b,
                    const float* __restrict__ Wd,
                    const float* __restrict__ bd,
                    float* __restrict__ out)
{
    extern __shared__ float smem[];
    float* sWk = smem + OFF_WK;
    float* sWr = smem + OFF_WR;
    float* sb  = smem + OFF_B;
    float* sWd = smem + OFF_WD;
    float* sx  = smem + OFF_X;
    float* sh  = smem + OFF_H;

    const int tid  = threadIdx.x;
    const int row0 = blockIdx.x * ROWS;

    // ---- cooperative weight load (float4 coalesced) ----
    {
        const float4* g;
        float4* s;
        g = (const float4*)Wk; s = (float4*)sWk;
        for (int i = tid; i < (F_DIM*G_DIM)/4; i += THREADS) s[i] = g[i];
        g = (const float4*)Wr; s = (float4*)sWr;
        for (int i = tid; i < (H_DIM*G_DIM)/4; i += THREADS) s[i] = g[i];
        g = (const float4*)b;  s = (float4*)sb;
        for (int i = tid; i < G_DIM/4; i += THREADS) s[i] = g[i];
        g = (const float4*)Wd; s = (float4*)sWd;
        for (int i = tid; i < (H_DIM*NL)/4; i += THREADS) s[i] = g[i];
        for (int i = tid; i < ROWS*H_DIM; i += THREADS) sh[i] = 0.0f;  // h0 = 0
    }

    // thread micro-tile: rows r0..r0+3, hidden units u0,u0+1 across 4 gates
    const int tc = tid & 31;
    const int tr = tid >> 5;
    const int r0 = tr * 4;
    const int u0 = 2 * tc;

    float c_st[4][2] = {{0.f,0.f},{0.f,0.f},{0.f,0.f},{0.f,0.f}};  // cell state

    for (int t = 0; t < T_LEN; ++t) {
        // A: stage x[:, t, :] tile into SMEM (float4; 92 = 23*4 floats/row)
        for (int q = tid; q < ROWS * (F_DIM/4); q += THREADS) {
            int row  = q / (F_DIM/4);
            int quad = q - row * (F_DIM/4);
            float4 v = *(const float4*)(x + ((size_t)(row0 + row) * T_LEN + t) * F_DIM + quad * 4);
            *(float4*)(sx + row * F_DIM + quad * 4) = v;
        }
        __syncthreads();

        // C: z = x_t @ Wk + h @ Wr + b   (packed f32x2 microkernel)
        ull acc[4][4];
        {
            ull b0 = *(const ull*)(sb + u0);
            ull b1 = *(const ull*)(sb + 64  + u0);
            ull b2 = *(const ull*)(sb + 128 + u0);
            ull b3 = *(const ull*)(sb + 192 + u0);
            #pragma unroll
            for (int i = 0; i < 4; ++i) {
                acc[i][0] = b0; acc[i][1] = b1; acc[i][2] = b2; acc[i][3] = b3;
            }
        }
        #pragma unroll 2
        for (int f = 0; f < F_DIM; ++f) {
            const float* wrow = sWk + f * G_DIM + u0;
            ull w0 = *(const ull*)(wrow);
            ull w1 = *(const ull*)(wrow + 64);
            ull w2 = *(const ull*)(wrow + 128);
            ull w3 = *(const ull*)(wrow + 192);
            #pragma unroll
            for (int i = 0; i < 4; ++i) {
                ull a = pack2(sx[(r0 + i) * F_DIM + f]);
                fma2(acc[i][0], a, w0);
                fma2(acc[i][1], a, w1);
                fma2(acc[i][2], a, w2);
                fma2(acc[i][3], a, w3);
            }
        }
        #pragma unroll 2
        for (int j = 0; j < H_DIM; ++j) {
            const float* wrow = sWr + j * G_DIM + u0;
            ull w0 = *(const ull*)(wrow);
            ull w1 = *(const ull*)(wrow + 64);
            ull w2 = *(const ull*)(wrow + 128);
            ull w3 = *(const ull*)(wrow + 192);
            #pragma unroll
            for (int i = 0; i < 4; ++i) {
                ull a = pack2(sh[(r0 + i) * H_DIM + j]);
                fma2(acc[i][0], a, w0);
                fma2(acc[i][1], a, w1);
                fma2(acc[i][2], a, w2);
                fma2(acc[i][3], a, w3);
            }
        }
        __syncthreads();   // all reads of sh(t-1)/sx(t) done before updates

        // E: gates -> cell/hidden update, write h to SMEM
        #pragma unroll
        for (int i = 0; i < 4; ++i) {
            float2 zi = unpack2(acc[i][0]);
            float2 zf = unpack2(acc[i][1]);
            float2 zg = unpack2(acc[i][2]);
            float2 zo = unpack2(acc[i][3]);
            float h0, h1;
            {
                float ig = sig_acc(zi.x), fg = sig_acc(zf.x);
                float gg = tanh_acc(zg.x), og = sig_acc(zo.x);
                float c = fg * c_st[i][0] + ig * gg;
                c_st[i][0] = c;
                h0 = og * tanh_acc(c);
            }
            {
                float ig = sig_acc(zi.y), fg = sig_acc(zf.y);
                float gg = tanh_acc(zg.y), og = sig_acc(zo.y);
                float c = fg * c_st[i][1] + ig * gg;
                c_st[i][1] = c;
                h1 = og * tanh_acc(c);
            }
            *(float2*)(sh + (r0 + i) * H_DIM + u0) = make_float2(h0, h1);
        }
    }
    __syncthreads();

    // head: out[r, l] = sigmoid(h_final @ Wd + bd)
    if (tid < ROWS * NL) {
        int r = tid >> 1;
        int l = tid & 1;
        float s = bd[l];
        const float* hr = sh + r * H_DIM;
        #pragma unroll 8
        for (int j = 0; j < H_DIM; ++j)
            s += hr[j] * sWd[j * NL + l];
        out[(size_t)(row0 + r) * NL + l] = sig_acc(s);
    }
}

extern "C" void kernel_launch(void* const* d_in, const int* in_sizes, int n_in,
                              void* d_out, int out_size)
{
    const float* x  = (const float*)d_in[0];
    const float* Wk = (const float*)d_in[1];
    const float* Wr = (const float*)d_in[2];
    const float* b  = (const float*)d_in[3];
    const float* Wd = (const float*)d_in[4];
    const float* bd = (const float*)d_in[5];
    float* out = (float*)d_out;

    cudaFuncSetAttribute(lstm_persist_kernel,
                         cudaFuncAttributeMaxDynamicSharedMemorySize, SMEM_BYTES);
    lstm_persist_kernel<<<B_TOT / ROWS, THREADS, SMEM_BYTES>>>(x, Wk, Wr, b, Wd, bd, out);
}

// round 5
// speedup vs baseline: 2.3089x; 2.3089x over previous
#include <cuda_runtime.h>
#include <cuda_fp16.h>
#include <cstdint>

#define B_TOT   32768
#define T_LEN   40
#define F_DIM   92
#define H_DIM   64
#define G_DIM   256
#define ROWS    128
#define THREADS 256
#define KP      160      // k: 0..91 x, 92..95 pad, 96..159 h
#define NKC     10

// ---------------- SMEM byte offsets ----------------
#define W_OFF    0                 // fp16 W frag layout [kc][n][t]{8B} : 10*256*32 = 81920
#define AH_OFF   81920             // fp16 A-hi frags: [mtg(8)][kc(10)][lane(32)]{16B} = 40960
#define AL_OFF   122880            // fp16 A-lo: 40960
#define XS_OFF   163840            // fp32 x stage [128][92] = 47104
#define SB_OFF   210944            // bias fp32 [256] = 1024
#define SWD_OFF  211968            // Wd fp32 [64][2] = 512
#define SMEM_BYTES 212480

typedef unsigned int uint;

__device__ __forceinline__ uint32_t smem_u32(const void* p) {
    uint32_t a;
    asm("{ .reg .u64 t; cvta.to.shared.u64 t, %1; cvt.u32.u64 %0, t; }" : "=r"(a) : "l"(p));
    return a;
}
__device__ __forceinline__ void cp_async16(uint32_t dst, const void* src) {
    asm volatile("cp.async.cg.shared.global [%0], [%1], 16;" :: "r"(dst), "l"(src) : "memory");
}
#define CP_COMMIT() asm volatile("cp.async.commit_group;" ::: "memory")
#define CP_WAIT0()  asm volatile("cp.async.wait_group 0;" ::: "memory")

__device__ __forceinline__ void mma16816(float* d, const uint4& a, const uint2& b) {
    asm volatile(
        "mma.sync.aligned.m16n8k16.row.col.f32.f16.f16.f32 "
        "{%0,%1,%2,%3}, {%4,%5,%6,%7}, {%8,%9}, {%0,%1,%2,%3};"
        : "+f"(d[0]), "+f"(d[1]), "+f"(d[2]), "+f"(d[3])
        : "r"(a.x), "r"(a.y), "r"(a.z), "r"(a.w), "r"(b.x), "r"(b.y));
}

__device__ __forceinline__ float sig_acc(float x) { return 1.0f / (1.0f + __expf(-x)); }
__device__ __forceinline__ float tanh_acc(float x) {
    float a = fabsf(x);
    float e = __expf(-2.0f * a);
    float t = (1.0f - e) / (1.0f + e);
    return copysignf(t, x);
}

// A-plane byte offset for element (row, k); k even pairs are contiguous 4B
__device__ __forceinline__ int a_addr(int row, int k) {
    int mtg = row >> 4, r16 = row & 15, g = r16 & 7;
    int kc = k >> 4, kr = k & 15, tK = (kr >> 1) & 3;
    return (((mtg * NKC + kc) * 32 + g * 4 + tK) << 4) + ((kr >> 3) << 3) + ((r16 >> 3) << 2);
}

__global__ void __launch_bounds__(THREADS, 1)
lstm_hmma_kernel(const float* __restrict__ x,
                 const float* __restrict__ Wk,
                 const float* __restrict__ Wr,
                 const float* __restrict__ b,
                 const float* __restrict__ Wd,
                 const float* __restrict__ bd,
                 float* __restrict__ out)
{
    extern __shared__ char smem_c[];
    float* XS  = (float*)(smem_c + XS_OFF);
    float* sb  = (float*)(smem_c + SB_OFF);
    float* sWd = (float*)(smem_c + SWD_OFF);
    const uint32_t sbase = smem_u32(smem_c);

    const int tid  = threadIdx.x;
    const int w    = tid >> 5;
    const int lane = tid & 31;
    const int g    = lane >> 2;      // mma group id
    const int tt   = lane & 3;       // mma thread-in-group
    const int wm   = w >> 1;         // warp M index (0..3): rows 32*wm..+31
    const int wu   = w & 1;          // warp unit-half (0..1): units 32*wu..+31
    const int row0 = blockIdx.x * ROWS;

    // ---------------- prologue ----------------
    // zero A planes (hi+lo contiguous)
    for (int i = tid; i < (2 * 40960) / 16; i += THREADS)
        *(uint4*)(smem_c + AH_OFF + i * 16) = make_uint4(0, 0, 0, 0);

    // cp.async x(t=0) -> XS
    for (int i = tid; i < ROWS * 23; i += THREADS) {
        int r = i / 23, q = i - r * 23;
        cp_async16(sbase + XS_OFF + (r * F_DIM + q * 4) * 4,
                   x + ((size_t)(row0 + r) * T_LEN + 0) * F_DIM + q * 4);
    }
    CP_COMMIT();

    // W -> fp16 frag-permuted SMEM
    for (int idx = tid; idx < KP * G_DIM; idx += THREADS) {
        int n = idx & 255, k = idx >> 8;
        float v;
        if (k < F_DIM)       v = Wk[k * G_DIM + n];
        else if (k < 96)     v = 0.0f;
        else                 v = Wr[(k - 96) * G_DIM + n];
        int kr = k & 15;
        int addr = W_OFF + (k >> 4) * 8192 + n * 32 + ((kr >> 1) & 3) * 8
                 + ((kr >> 3) << 2) + ((kr & 1) << 1);
        *(__half*)(smem_c + addr) = __float2half_rn(v);
    }
    if (tid < G_DIM) sb[tid] = b[tid];
    if (tid < H_DIM * 2) sWd[tid] = Wd[tid];

    CP_WAIT0();
    __syncthreads();

    // convert XS(0) -> A planes (x region incl. zero pads 92..95)
    {
        int r = tid >> 1, kh = (tid & 1) * 48;
        #pragma unroll
        for (int p = 0; p < 24; ++p) {
            int k = kh + 2 * p;
            float2 v = (k < F_DIM) ? *(float2*)(XS + r * F_DIM + k) : make_float2(0.f, 0.f);
            __half2 hi = __floats2half2_rn(v.x, v.y);
            float2 hf = __half22float2(hi);
            __half2 lo = __floats2half2_rn(v.x - hf.x, v.y - hf.y);
            int ad = a_addr(r, k);
            *(uint*)(smem_c + AH_OFF + ad) = *(uint*)&hi;
            *(uint*)(smem_c + AL_OFF + ad) = *(uint*)&lo;
        }
    }
    __syncthreads();

    float c_st[32];
    #pragma unroll
    for (int i = 0; i < 32; ++i) c_st[i] = 0.0f;

    // ---------------- time loop ----------------
    for (int t = 0; t < T_LEN; ++t) {
        // prefetch x(t+1) under MMA
        if (t + 1 < T_LEN) {
            for (int i = tid; i < ROWS * 23; i += THREADS) {
                int r = i / 23, q = i - r * 23;
                cp_async16(sbase + XS_OFF + (r * F_DIM + q * 4) * 4,
                           x + ((size_t)(row0 + r) * T_LEN + (t + 1)) * F_DIM + q * 4);
            }
            CP_COMMIT();
        }

        // acc init = bias
        float acc[2][16][4];
        #pragma unroll
        for (int nt = 0; nt < 16; ++nt) {
            int col = ((nt >> 2) << 6) + wu * 32 + ((nt & 3) << 3) + 2 * tt;
            float2 bv = *(const float2*)(sb + col);
            #pragma unroll
            for (int mt = 0; mt < 2; ++mt) {
                acc[mt][nt][0] = bv.x; acc[mt][nt][1] = bv.y;
                acc[mt][nt][2] = bv.x; acc[mt][nt][3] = bv.y;
            }
        }

        // MMA: 2 passes (A-hi, A-lo) fused per kc
        for (int kc = 0; kc < NKC; ++kc) {
            int a0off = (((wm * 2 + 0) * NKC + kc) * 32 + lane) << 4;
            int a1off = (((wm * 2 + 1) * NKC + kc) * 32 + lane) << 4;
            uint4 ah0 = *(const uint4*)(smem_c + AH_OFF + a0off);
            uint4 al0 = *(const uint4*)(smem_c + AL_OFF + a0off);
            uint4 ah1 = *(const uint4*)(smem_c + AH_OFF + a1off);
            uint4 al1 = *(const uint4*)(smem_c + AL_OFF + a1off);
            const char* wb = smem_c + W_OFF + kc * 8192 + (wu * 32 + g) * 32 + tt * 8;
            #pragma unroll
            for (int nt = 0; nt < 16; ++nt) {
                int noff = ((((nt >> 2) << 6) + ((nt & 3) << 3)) << 5);
                uint2 b2 = *(const uint2*)(wb + noff);
                mma16816(acc[0][nt], ah0, b2);
                mma16816(acc[0][nt], al0, b2);
                mma16816(acc[1][nt], ah1, b2);
                mma16816(acc[1][nt], al1, b2);
            }
        }
        __syncthreads();   // all MMA reads of A done

        // epilogue: gates -> c,h ; write h (fp16 hi+lo) into A h-region
        #pragma unroll
        for (int mt = 0; mt < 2; ++mt) {
            int mtg = wm * 2 + mt;
            #pragma unroll
            for (int ut = 0; ut < 4; ++ut) {
                float hv[4];
                #pragma unroll
                for (int s = 0; s < 4; ++s) {
                    int ci = mt * 16 + ut * 4 + s;
                    float ig = sig_acc(acc[mt][ut][s]);
                    float fg = sig_acc(acc[mt][4 + ut][s]);
                    float gg = tanh_acc(acc[mt][8 + ut][s]);
                    float og = sig_acc(acc[mt][12 + ut][s]);
                    float cn = fg * c_st[ci] + ig * gg;
                    c_st[ci] = cn;
                    hv[s] = og * tanh_acc(cn);
                }
                int u0 = wu * 32 + ut * 8 + 2 * tt;
                int k  = 96 + u0;
                int kc = k >> 4, kr = k & 15, tK = (kr >> 1) & 3;
                int base = (((mtg * NKC + kc) * 32 + g * 4 + tK) << 4) + ((kr >> 3) << 3);
                __half2 h01 = __floats2half2_rn(hv[0], hv[1]);
                __half2 h23 = __floats2half2_rn(hv[2], hv[3]);
                float2 f01 = __half22float2(h01);
                float2 f23 = __half22float2(h23);
                __half2 l01 = __floats2half2_rn(hv[0] - f01.x, hv[1] - f01.y);
                __half2 l23 = __floats2half2_rn(hv[2] - f23.x, hv[3] - f23.y);
                *(uint*)(smem_c + AH_OFF + base)     = *(uint*)&h01;  // rows g
                *(uint*)(smem_c + AH_OFF + base + 4) = *(uint*)&h23;  // rows g+8
                *(uint*)(smem_c + AL_OFF + base)     = *(uint*)&l01;
                *(uint*)(smem_c + AL_OFF + base + 4) = *(uint*)&l23;
            }
        }

        // convert XS(t+1) -> A x-region
        if (t + 1 < T_LEN) {
            CP_WAIT0();
            int r = tid >> 1, kh = (tid & 1) * 48;
            #pragma unroll
            for (int p = 0; p < 24; ++p) {
                int k = kh + 2 * p;
                float2 v = (k < F_DIM) ? *(float2*)(XS + r * F_DIM + k) : make_float2(0.f, 0.f);
                __half2 hi = __floats2half2_rn(v.x, v.y);
                float2 hf = __half22float2(hi);
                __half2 lo = __floats2half2_rn(v.x - hf.x, v.y - hf.y);
                int ad = a_addr(r, k);
                *(uint*)(smem_c + AH_OFF + ad) = *(uint*)&hi;
                *(uint*)(smem_c + AL_OFF + ad) = *(uint*)&lo;
            }
        }
        __syncthreads();
    }

    // ---------------- head ----------------
    {
        int r = tid >> 1, l = tid & 1;
        float s = bd[l];
        #pragma unroll
        for (int up = 0; up < 32; ++up) {
            int u = 2 * up;
            int ad = a_addr(r, 96 + u);
            uint hb = *(uint*)(smem_c + AH_OFF + ad);
            uint lb = *(uint*)(smem_c + AL_OFF + ad);
            float2 hf = __half22float2(*(__half2*)&hb);
            float2 lf = __half22float2(*(__half2*)&lb);
            s += (hf.x + lf.x) * sWd[u * 2 + l] + (hf.y + lf.y) * sWd[(u + 1) * 2 + l];
        }
        out[(size_t)(row0 + r) * 2 + l] = sig_acc(s);
    }
}

extern "C" void kernel_launch(void* const* d_in, const int* in_sizes, int n_in,
                              void* d_out, int out_size)
{
    const float* x  = (const float*)d_in[0];
    const float* Wk = (const float*)d_in[1];
    const float* Wr = (const float*)d_in[2];
    const float* b  = (const float*)d_in[3];
    const float* Wd = (const float*)d_in[4];
    const float* bd = (const float*)d_in[5];
    float* out = (float*)d_out;

    cudaFuncSetAttribute(lstm_hmma_kernel,
                         cudaFuncAttributeMaxDynamicSharedMemorySize, SMEM_BYTES);
    lstm_hmma_kernel<<<B_TOT / ROWS, THREADS, SMEM_BYTES>>>(x, Wk, Wr, b, Wd, bd, out);
}

// round 6
// speedup vs baseline: 3.9814x; 1.7244x over previous
#include <cuda_runtime.h>
#include <cuda_fp16.h>
#include <cstdint>

#define B_TOT   32768
#define T_LEN   40
#define F_DIM   92
#define H_DIM   64
#define G_DIM   256
#define ROWS    128
#define THREADS 512
#define KP      160      // k: 0..91 x, 92..95 pad, 96..159 h
#define NKC     10

// ---------------- SMEM byte offsets ----------------
#define W_OFF    0                 // fp16 W frag layout [kc][n][t]{8B} : 10*256*32 = 81920
#define AH_OFF   81920             // fp16 A frags: [mtg(8)][kc(10)][lane(32)]{16B} = 40960
#define XS_OFF   122880            // fp32 x stage [128][92] = 47104
#define SB_OFF   169984            // bias fp32 [256] = 1024
#define SWD_OFF  171008            // Wd fp32 [64][2] = 512
#define SMEM_BYTES 171520

typedef unsigned int uint;

__device__ __forceinline__ uint32_t smem_u32(const void* p) {
    uint32_t a;
    asm("{ .reg .u64 t; cvta.to.shared.u64 t, %1; cvt.u32.u64 %0, t; }" : "=r"(a) : "l"(p));
    return a;
}
__device__ __forceinline__ void cp_async16(uint32_t dst, const void* src) {
    asm volatile("cp.async.cg.shared.global [%0], [%1], 16;" :: "r"(dst), "l"(src) : "memory");
}
#define CP_COMMIT() asm volatile("cp.async.commit_group;" ::: "memory")
#define CP_WAIT0()  asm volatile("cp.async.wait_group 0;" ::: "memory")

__device__ __forceinline__ void mma16816(float* d, const uint4& a, const uint2& b) {
    asm volatile(
        "mma.sync.aligned.m16n8k16.row.col.f32.f16.f16.f32 "
        "{%0,%1,%2,%3}, {%4,%5,%6,%7}, {%8,%9}, {%0,%1,%2,%3};"
        : "+f"(d[0]), "+f"(d[1]), "+f"(d[2]), "+f"(d[3])
        : "r"(a.x), "r"(a.y), "r"(a.z), "r"(a.w), "r"(b.x), "r"(b.y));
}

__device__ __forceinline__ float sig_acc(float x) { return 1.0f / (1.0f + __expf(-x)); }
__device__ __forceinline__ float tanh_acc(float x) {
    float a = fabsf(x);
    float e = __expf(-2.0f * a);
    float t = (1.0f - e) / (1.0f + e);
    return copysignf(t, x);
}

// A-plane byte offset for element (row, k); k even pairs contiguous 4B
__device__ __forceinline__ int a_addr(int row, int k) {
    int mtg = row >> 4, r16 = row & 15, g = r16 & 7;
    int kc = k >> 4, kr = k & 15, tK = (kr >> 1) & 3;
    return (((mtg * NKC + kc) * 32 + g * 4 + tK) << 4) + ((kr >> 3) << 3) + ((r16 >> 3) << 2);
}

__global__ void __launch_bounds__(THREADS, 1)
lstm_hmma_kernel(const float* __restrict__ x,
                 const float* __restrict__ Wk,
                 const float* __restrict__ Wr,
                 const float* __restrict__ b,
                 const float* __restrict__ Wd,
                 const float* __restrict__ bd,
                 float* __restrict__ out)
{
    extern __shared__ char smem_c[];
    float* XS  = (float*)(smem_c + XS_OFF);
    float* sb  = (float*)(smem_c + SB_OFF);
    float* sWd = (float*)(smem_c + SWD_OFF);
    const uint32_t sbase = smem_u32(smem_c);

    const int tid  = threadIdx.x;
    const int w    = tid >> 5;
    const int lane = tid & 31;
    const int g    = lane >> 2;      // mma group id (row within half-tile)
    const int tt   = lane & 3;       // thread-in-group
    const int wm   = w >> 1;         // warp M index (0..7): rows 16*wm..+15
    const int wu   = w & 1;          // warp unit-half (0..1): units 32*wu..+31
    const int row0 = blockIdx.x * ROWS;

    // ---------------- prologue ----------------
    // zero A plane
    for (int i = tid; i < 40960 / 16; i += THREADS)
        *(uint4*)(smem_c + AH_OFF + i * 16) = make_uint4(0, 0, 0, 0);

    // cp.async x(t=0) -> XS
    for (int i = tid; i < ROWS * 23; i += THREADS) {
        int r = i / 23, q = i - r * 23;
        cp_async16(sbase + XS_OFF + (r * F_DIM + q * 4) * 4,
                   x + ((size_t)(row0 + r) * T_LEN + 0) * F_DIM + q * 4);
    }
    CP_COMMIT();

    // W -> fp16 frag-permuted SMEM
    for (int idx = tid; idx < KP * G_DIM; idx += THREADS) {
        int n = idx & 255, k = idx >> 8;
        float v;
        if (k < F_DIM)       v = Wk[k * G_DIM + n];
        else if (k < 96)     v = 0.0f;
        else                 v = Wr[(k - 96) * G_DIM + n];
        int kr = k & 15;
        int addr = W_OFF + (k >> 4) * 8192 + n * 32 + ((kr >> 1) & 3) * 8
                 + ((kr >> 3) << 2) + ((kr & 1) << 1);
        *(__half*)(smem_c + addr) = __float2half_rn(v);
    }
    if (tid < G_DIM) sb[tid] = b[tid];
    if (tid < H_DIM * 2) sWd[tid] = Wd[tid];

    CP_WAIT0();
    __syncthreads();

    // convert XS(0) -> A plane x-region (incl. zero pads 92..95)
    {
        int r = tid >> 2, kh = (tid & 3) * 24;
        #pragma unroll
        for (int p = 0; p < 12; ++p) {
            int k = kh + 2 * p;
            float2 v = (k < F_DIM) ? *(float2*)(XS + r * F_DIM + k) : make_float2(0.f, 0.f);
            __half2 hi = __floats2half2_rn(v.x, v.y);
            *(uint*)(smem_c + AH_OFF + a_addr(r, k)) = *(uint*)&hi;
        }
    }
    __syncthreads();

    float c_st[16];
    #pragma unroll
    for (int i = 0; i < 16; ++i) c_st[i] = 0.0f;

    // ---------------- time loop ----------------
    for (int t = 0; t < T_LEN; ++t) {
        // prefetch x(t+1) under MMA
        if (t + 1 < T_LEN) {
            for (int i = tid; i < ROWS * 23; i += THREADS) {
                int r = i / 23, q = i - r * 23;
                cp_async16(sbase + XS_OFF + (r * F_DIM + q * 4) * 4,
                           x + ((size_t)(row0 + r) * T_LEN + (t + 1)) * F_DIM + q * 4);
            }
            CP_COMMIT();
        }

        // acc init = bias
        float acc[16][4];
        #pragma unroll
        for (int nt = 0; nt < 16; ++nt) {
            int col = ((nt >> 2) << 6) + wu * 32 + ((nt & 3) << 3) + 2 * tt;
            float2 bv = *(const float2*)(sb + col);
            acc[nt][0] = bv.x; acc[nt][1] = bv.y;
            acc[nt][2] = bv.x; acc[nt][3] = bv.y;
        }

        // MMA: single fp16 pass over 10 K-chunks
        #pragma unroll
        for (int kc = 0; kc < NKC; ++kc) {
            int aoff = ((wm * NKC + kc) * 32 + lane) << 4;
            uint4 af = *(const uint4*)(smem_c + AH_OFF + aoff);
            const char* wb = smem_c + W_OFF + kc * 8192 + (wu * 32 + g) * 32 + tt * 8;
            #pragma unroll
            for (int nt = 0; nt < 16; ++nt) {
                int noff = ((((nt >> 2) << 6) + ((nt & 3) << 3)) << 5);
                uint2 b2 = *(const uint2*)(wb + noff);
                mma16816(acc[nt], af, b2);
            }
        }
        __syncthreads();   // all MMA reads of A done

        // epilogue: gates -> c,h ; write h (fp16) into A h-region
        #pragma unroll
        for (int ut = 0; ut < 4; ++ut) {
            float hv[4];
            #pragma unroll
            for (int s = 0; s < 4; ++s) {
                int ci = ut * 4 + s;
                float ig = sig_acc(acc[ut][s]);
                float fg = sig_acc(acc[4 + ut][s]);
                float gg = tanh_acc(acc[8 + ut][s]);
                float og = sig_acc(acc[12 + ut][s]);
                float cn = fg * c_st[ci] + ig * gg;
                c_st[ci] = cn;
                hv[s] = og * tanh_acc(cn);
            }
            int u0 = wu * 32 + ut * 8 + 2 * tt;
            int k  = 96 + u0;
            int kc = k >> 4, kr = k & 15, tK = (kr >> 1) & 3;
            int base = (((wm * NKC + kc) * 32 + g * 4 + tK) << 4) + ((kr >> 3) << 3);
            __half2 h01 = __floats2half2_rn(hv[0], hv[1]);   // row g
            __half2 h23 = __floats2half2_rn(hv[2], hv[3]);   // row g+8
            *(uint*)(smem_c + AH_OFF + base)     = *(uint*)&h01;
            *(uint*)(smem_c + AH_OFF + base + 4) = *(uint*)&h23;
        }

        // convert XS(t+1) -> A x-region
        if (t + 1 < T_LEN) {
            CP_WAIT0();
            int r = tid >> 2, kh = (tid & 3) * 24;
            #pragma unroll
            for (int p = 0; p < 12; ++p) {
                int k = kh + 2 * p;
                float2 v = (k < F_DIM) ? *(float2*)(XS + r * F_DIM + k) : make_float2(0.f, 0.f);
                __half2 hi = __floats2half2_rn(v.x, v.y);
                *(uint*)(smem_c + AH_OFF + a_addr(r, k)) = *(uint*)&hi;
            }
        }
        __syncthreads();
    }

    // ---------------- head ----------------
    if (tid < ROWS * 2) {
        int r = tid >> 1, l = tid & 1;
        float s = bd[l];
        #pragma unroll
        for (int up = 0; up < 32; ++up) {
            int u = 2 * up;
            uint hb = *(uint*)(smem_c + AH_OFF + a_addr(r, 96 + u));
            float2 hf = __half22float2(*(__half2*)&hb);
            s += hf.x * sWd[u * 2 + l] + hf.y * sWd[(u + 1) * 2 + l];
        }
        out[(size_t)(row0 + r) * 2 + l] = sig_acc(s);
    }
}

extern "C" void kernel_launch(void* const* d_in, const int* in_sizes, int n_in,
                              void* d_out, int out_size)
{
    const float* x  = (const float*)d_in[0];
    const float* Wk = (const float*)d_in[1];
    const float* Wr = (const float*)d_in[2];
    const float* b  = (const float*)d_in[3];
    const float* Wd = (const float*)d_in[4];
    const float* bd = (const float*)d_in[5];
    float* out = (float*)d_out;

    cudaFuncSetAttribute(lstm_hmma_kernel,
                         cudaFuncAttributeMaxDynamicSharedMemorySize, SMEM_BYTES);
    lstm_hmma_kernel<<<B_TOT / ROWS, THREADS, SMEM_BYTES>>>(x, Wk, Wr, b, Wd, bd, out);
}

// round 8
// speedup vs baseline: 4.5381x; 1.1398x over previous
#include <cuda_runtime.h>
#include <cuda_fp16.h>
#include <cstdint>

#define B_TOT   32768
#define T_LEN   40
#define F_DIM   92
#define H_DIM   64
#define G_DIM   256
#define ROWS    128
#define THREADS 512
#define KP      160      // k: 0..91 x, 92..95 pad, 96..159 h
#define NKC     10

// ---------------- SMEM byte offsets ----------------
#define W_OFF    0                 // fp16 W: [kc][blk=wc*4+gate][lane]{16B} : 10*16*512 = 81920
#define AH_OFF   81920             // fp16 A frags: [mtg(8)][kc(10)][lane(32)]{16B} = 40960
#define XS_OFF   122880            // fp32 x stage [128][92] = 47104
#define SB_OFF   169984            // bias fp32 [256] = 1024
#define SWD_OFF  171008            // Wd fp32 [64][2] = 512
#define SMEM_BYTES 171520

typedef unsigned int uint;

__device__ __forceinline__ uint32_t smem_u32(const void* p) {
    uint32_t a;
    asm("{ .reg .u64 t; cvta.to.shared.u64 t, %1; cvt.u32.u64 %0, t; }" : "=r"(a) : "l"(p));
    return a;
}
__device__ __forceinline__ void cp_async16(uint32_t dst, const void* src) {
    asm volatile("cp.async.cg.shared.global [%0], [%1], 16;" :: "r"(dst), "l"(src) : "memory");
}
#define CP_COMMIT() asm volatile("cp.async.commit_group;" ::: "memory")
#define CP_WAIT0()  asm volatile("cp.async.wait_group 0;" ::: "memory")

__device__ __forceinline__ void mma16816(float* d, const uint4& a, uint b0, uint b1) {
    asm volatile(
        "mma.sync.aligned.m16n8k16.row.col.f32.f16.f16.f32 "
        "{%0,%1,%2,%3}, {%4,%5,%6,%7}, {%8,%9}, {%0,%1,%2,%3};"
        : "+f"(d[0]), "+f"(d[1]), "+f"(d[2]), "+f"(d[3])
        : "r"(a.x), "r"(a.y), "r"(a.z), "r"(a.w), "r"(b0), "r"(b1));
}

__device__ __forceinline__ float tanh_ap(float x) {
    float r; asm("tanh.approx.f32 %0, %1;" : "=f"(r) : "f"(x)); return r;
}
__device__ __forceinline__ float sig_ap(float x) {
    return fmaf(0.5f, tanh_ap(0.5f * x), 0.5f);
}
__device__ __forceinline__ float sig_acc(float x) { return 1.0f / (1.0f + __expf(-x)); }

// A-plane byte offset for element (row, k); k even pairs contiguous 4B
__device__ __forceinline__ int a_addr(int row, int k) {
    int mtg = row >> 4, r16 = row & 15, g = r16 & 7;
    int kc = k >> 4, kr = k & 15, tK = (kr >> 1) & 3;
    return (((mtg * NKC + kc) * 32 + g * 4 + tK) << 4) + ((kr >> 3) << 3) + ((r16 >> 3) << 2);
}

__global__ void __launch_bounds__(THREADS, 1)
lstm_hmma_kernel(const float* __restrict__ x,
                 const float* __restrict__ Wk,
                 const float* __restrict__ Wr,
                 const float* __restrict__ b,
                 const float* __restrict__ Wd,
                 const float* __restrict__ bd,
                 float* __restrict__ out)
{
    extern __shared__ char smem_c[];
    float* XS  = (float*)(smem_c + XS_OFF);
    float* sb  = (float*)(smem_c + SB_OFF);
    float* sWd = (float*)(smem_c + SWD_OFF);
    const uint32_t sbase = smem_u32(smem_c);

    const int tid  = threadIdx.x;
    const int w    = tid >> 5;
    const int lane = tid & 31;
    const int g    = lane >> 2;      // mma group id
    const int tt   = lane & 3;       // thread-in-group
    const int wr   = w >> 2;         // warp row-group (0..3): rows 32*wr..+31
    const int wc   = w & 3;          // warp unit-group (0..3): units 16*wc..+15
    const int row0 = blockIdx.x * ROWS;

    // ---------------- prologue ----------------
    for (int i = tid; i < 40960 / 16; i += THREADS)
        *(uint4*)(smem_c + AH_OFF + i * 16) = make_uint4(0, 0, 0, 0);

    for (int i = tid; i < ROWS * 23; i += THREADS) {
        int r = i / 23, q = i - r * 23;
        cp_async16(sbase + XS_OFF + (r * F_DIM + q * 4) * 4,
                   x + ((size_t)(row0 + r) * T_LEN + 0) * F_DIM + q * 4);
    }
    CP_COMMIT();

    // W -> fp16 frag-permuted SMEM (paired-ng layout for LDS.128 B loads)
    for (int idx = tid; idx < KP * G_DIM; idx += THREADS) {
        int n = idx & 255, k = idx >> 8;
        float v;
        if (k < F_DIM)       v = Wk[k * G_DIM + n];
        else if (k < 96)     v = 0.0f;
        else                 v = Wr[(k - 96) * G_DIM + n];
        int kc = k >> 4, kr = k & 15;
        int gate = n >> 6, wcs = (n >> 4) & 3, ng = (n >> 3) & 1, gs = n & 7;
        int tts = (kr >> 1) & 3;
        int pos = ((kr >> 3) << 2) + ((kr & 1) << 1);
        int addr = W_OFF + kc * 8192 + (wcs * 4 + gate) * 512
                 + (gs * 4 + tts) * 16 + ng * 8 + pos;
        *(__half*)(smem_c + addr) = __float2half_rn(v);
    }
    if (tid < G_DIM) sb[tid] = b[tid];
    if (tid < H_DIM * 2) sWd[tid] = Wd[tid];

    CP_WAIT0();
    __syncthreads();

    // convert XS(0) -> A plane x-region (incl. zero pads 92..95)
    {
        int r = tid >> 2, kh = (tid & 3) * 24;
        #pragma unroll
        for (int p = 0; p < 12; ++p) {
            int k = kh + 2 * p;
            float2 v = (k < F_DIM) ? *(float2*)(XS + r * F_DIM + k) : make_float2(0.f, 0.f);
            __half2 hi = __floats2half2_rn(v.x, v.y);
            *(uint*)(smem_c + AH_OFF + a_addr(r, k)) = *(uint*)&hi;
        }
    }
    __syncthreads();

    float c_st[16];
    #pragma unroll
    for (int i = 0; i < 16; ++i) c_st[i] = 0.0f;

    // ---------------- time loop ----------------
    for (int t = 0; t < T_LEN; ++t) {
        if (t + 1 < T_LEN) {
            for (int i = tid; i < ROWS * 23; i += THREADS) {
                int r = i / 23, q = i - r * 23;
                cp_async16(sbase + XS_OFF + (r * F_DIM + q * 4) * 4,
                           x + ((size_t)(row0 + r) * T_LEN + (t + 1)) * F_DIM + q * 4);
            }
            CP_COMMIT();
        }

        // acc[mt][gate*2+ng][4], init = bias
        float acc[2][8][4];
        #pragma unroll
        for (int j = 0; j < 8; ++j) {
            int gate = j >> 1, ng = j & 1;
            int col = gate * 64 + wc * 16 + ng * 8 + 2 * tt;
            float2 bv = *(const float2*)(sb + col);
            #pragma unroll
            for (int mt = 0; mt < 2; ++mt) {
                acc[mt][j][0] = bv.x; acc[mt][j][1] = bv.y;
                acc[mt][j][2] = bv.x; acc[mt][j][3] = bv.y;
            }
        }

        // MMA over 10 K-chunks
        #pragma unroll
        for (int kc = 0; kc < NKC; ++kc) {
            int a0off = (((2 * wr + 0) * NKC + kc) * 32 + lane) << 4;
            int a1off = (((2 * wr + 1) * NKC + kc) * 32 + lane) << 4;
            uint4 a0 = *(const uint4*)(smem_c + AH_OFF + a0off);
            uint4 a1 = *(const uint4*)(smem_c + AH_OFF + a1off);
            const char* wb = smem_c + W_OFF + kc * 8192 + wc * 2048 + (g * 4 + tt) * 16;
            #pragma unroll
            for (int gate = 0; gate < 4; ++gate) {
                uint4 bq = *(const uint4*)(wb + gate * 512);
                mma16816(acc[0][gate * 2 + 0], a0, bq.x, bq.y);
                mma16816(acc[0][gate * 2 + 1], a0, bq.z, bq.w);
                mma16816(acc[1][gate * 2 + 0], a1, bq.x, bq.y);
                mma16816(acc[1][gate * 2 + 1], a1, bq.z, bq.w);
            }
        }
        __syncthreads();   // all MMA reads of A done

        // epilogue: gates -> c,h ; write h (fp16) into A h-region
        #pragma unroll
        for (int mt = 0; mt < 2; ++mt) {
            int mtg = wr * 2 + mt;
            #pragma unroll
            for (int ng = 0; ng < 2; ++ng) {
                float hv[4];
                #pragma unroll
                for (int s = 0; s < 4; ++s) {
                    int ci = mt * 8 + ng * 4 + s;
                    float ig = sig_ap(acc[mt][0 + ng][s]);
                    float fg = sig_ap(acc[mt][2 + ng][s]);
                    float gg = tanh_ap(acc[mt][4 + ng][s]);
                    float og = sig_ap(acc[mt][6 + ng][s]);
                    float cn = fmaf(fg, c_st[ci], ig * gg);
                    c_st[ci] = cn;
                    hv[s] = og * tanh_ap(cn);
                }
                int k  = 96 + wc * 16 + ng * 8 + 2 * tt;
                int kc = k >> 4, kr = k & 15, tK = (kr >> 1) & 3;
                int base = (((mtg * NKC + kc) * 32 + g * 4 + tK) << 4) + ((kr >> 3) << 3);
                __half2 h01 = __floats2half2_rn(hv[0], hv[1]);   // row g
                __half2 h23 = __floats2half2_rn(hv[2], hv[3]);   // row g+8
                uint2 hq = make_uint2(*(uint*)&h01, *(uint*)&h23);
                *(uint2*)(smem_c + AH_OFF + base) = hq;          // STS.64
            }
        }

        // convert XS(t+1) -> A x-region
        if (t + 1 < T_LEN) {
            CP_WAIT0();
            int r = tid >> 2, kh = (tid & 3) * 24;
            #pragma unroll
            for (int p = 0; p < 12; ++p) {
                int k = kh + 2 * p;
                float2 v = (k < F_DIM) ? *(float2*)(XS + r * F_DIM + k) : make_float2(0.f, 0.f);
                __half2 hi = __floats2half2_rn(v.x, v.y);
                *(uint*)(smem_c + AH_OFF + a_addr(r, k)) = *(uint*)&hi;
            }
        }
        __syncthreads();
    }

    // ---------------- head ----------------
    if (tid < ROWS * 2) {
        int r = tid >> 1, l = tid & 1;
        float s = bd[l];
        #pragma unroll
        for (int up = 0; up < 32; ++up) {
            int u = 2 * up;
            uint hb = *(uint*)(smem_c + AH_OFF + a_addr(r, 96 + u));
            float2 hf = __half22float2(*(__half2*)&hb);
            s += hf.x * sWd[u * 2 + l] + hf.y * sWd[(u + 1) * 2 + l];
        }
        out[(size_t)(row0 + r) * 2 + l] = sig_acc(s);
    }
}

extern "C" void kernel_launch(void* const* d_in, const int* in_sizes, int n_in,
                              void* d_out, int out_size)
{
    const float* x  = (const float*)d_in[0];
    const float* Wk = (const float*)d_in[1];
    const float* Wr = (const float*)d_in[2];
    const float* b  = (const float*)d_in[3];
    const float* Wd = (const float*)d_in[4];
    const float* bd = (const float*)d_in[5];
    float* out = (float*)d_out;

    cudaFuncSetAttribute(lstm_hmma_kernel,
                         cudaFuncAttributeMaxDynamicSharedMemorySize, SMEM_BYTES);
    lstm_hmma_kernel<<<B_TOT / ROWS, THREADS, SMEM_BYTES>>>(x, Wk, Wr, b, Wd, bd, out);
}

// round 9
// speedup vs baseline: 5.1943x; 1.1446x over previous
#include <cuda_runtime.h>
#include <cuda_fp16.h>
#include <cstdint>

#define B_TOT   32768
#define T_LEN   40
#define F_DIM   92
#define H_DIM   64
#define G_DIM   256
#define ROWS    128
#define THREADS 512
#define KP      160      // k: 0..91 x, 92..95 pad, 96..159 h
#define NKC     10

// ---------------- SMEM byte offsets ----------------
#define W_OFF    0                 // fp16 W: [kc][blk=wc*4+gate][lane]{16B} : 10*16*512 = 81920
#define A_OFF    81920             // fp16 A frags x2 buffers: [buf][mtg(8)][kc(10)][lane(32)]{16B} = 81920
#define A_BUFSZ  40960
#define XS_OFF   163840            // fp32 x stage [128][92] = 47104
#define SB_OFF   210944            // bias fp32 [256] = 1024
#define SWD_OFF  211968            // Wd fp32 [64][2] = 512
#define SMEM_BYTES 212480

typedef unsigned int uint;

__device__ __forceinline__ uint32_t smem_u32(const void* p) {
    uint32_t a;
    asm("{ .reg .u64 t; cvta.to.shared.u64 t, %1; cvt.u32.u64 %0, t; }" : "=r"(a) : "l"(p));
    return a;
}
__device__ __forceinline__ void cp_async16(uint32_t dst, const void* src) {
    asm volatile("cp.async.cg.shared.global [%0], [%1], 16;" :: "r"(dst), "l"(src) : "memory");
}
#define CP_COMMIT() asm volatile("cp.async.commit_group;" ::: "memory")
#define CP_WAIT0()  asm volatile("cp.async.wait_group 0;" ::: "memory")

__device__ __forceinline__ void mma16816(float* d, const uint4& a, uint b0, uint b1) {
    asm volatile(
        "mma.sync.aligned.m16n8k16.row.col.f32.f16.f16.f32 "
        "{%0,%1,%2,%3}, {%4,%5,%6,%7}, {%8,%9}, {%0,%1,%2,%3};"
        : "+f"(d[0]), "+f"(d[1]), "+f"(d[2]), "+f"(d[3])
        : "r"(a.x), "r"(a.y), "r"(a.z), "r"(a.w), "r"(b0), "r"(b1));
}

__device__ __forceinline__ float tanh_ap(float x) {
    float r; asm("tanh.approx.f32 %0, %1;" : "=f"(r) : "f"(x)); return r;
}
__device__ __forceinline__ float sig_ap(float x) {
    return fmaf(0.5f, tanh_ap(0.5f * x), 0.5f);
}
__device__ __forceinline__ float sig_acc(float x) { return 1.0f / (1.0f + __expf(-x)); }

// A-plane byte offset for element (row, k) within one buffer; k even pairs contiguous 4B
__device__ __forceinline__ int a_addr(int row, int k) {
    int mtg = row >> 4, r16 = row & 15, g = r16 & 7;
    int kc = k >> 4, kr = k & 15, tK = (kr >> 1) & 3;
    return (((mtg * NKC + kc) * 32 + g * 4 + tK) << 4) + ((kr >> 3) << 3) + ((r16 >> 3) << 2);
}

__global__ void __launch_bounds__(THREADS, 1)
lstm_hmma_kernel(const float* __restrict__ x,
                 const float* __restrict__ Wk,
                 const float* __restrict__ Wr,
                 const float* __restrict__ b,
                 const float* __restrict__ Wd,
                 const float* __restrict__ bd,
                 float* __restrict__ out)
{
    extern __shared__ char smem_c[];
    float* sb  = (float*)(smem_c + SB_OFF);
    float* sWd = (float*)(smem_c + SWD_OFF);
    const uint32_t sbase = smem_u32(smem_c);

    const int tid  = threadIdx.x;
    const int w    = tid >> 5;
    const int lane = tid & 31;
    const int g    = lane >> 2;      // mma group id
    const int tt   = lane & 3;       // thread-in-group
    const int wr   = w >> 2;         // warp row-group (0..3): rows 32*wr..+31
    const int wc   = w & 3;          // warp unit-group (0..3): units 16*wc..+15
    const int row0 = blockIdx.x * ROWS;

    // ---------------- prologue ----------------
    // zero both A buffers
    for (int i = tid; i < (2 * A_BUFSZ) / 16; i += THREADS)
        *(uint4*)(smem_c + A_OFF + i * 16) = make_uint4(0, 0, 0, 0);

    // cp.async x(t=0) -> XS
    for (int i = tid; i < ROWS * 23; i += THREADS) {
        int r = i / 23, q = i - r * 23;
        cp_async16(sbase + XS_OFF + (r * 23 + q) * 16,
                   x + ((size_t)(row0 + r) * T_LEN + 0) * F_DIM + q * 4);
    }
    CP_COMMIT();

    // W -> fp16 frag-permuted SMEM (paired-ng layout for LDS.128 B loads)
    for (int idx = tid; idx < KP * G_DIM; idx += THREADS) {
        int n = idx & 255, k = idx >> 8;
        float v;
        if (k < F_DIM)       v = Wk[k * G_DIM + n];
        else if (k < 96)     v = 0.0f;
        else                 v = Wr[(k - 96) * G_DIM + n];
        int kc = k >> 4, kr = k & 15;
        int gate = n >> 6, wcs = (n >> 4) & 3, ng = (n >> 3) & 1, gs = n & 7;
        int tts = (kr >> 1) & 3;
        int pos = ((kr >> 3) << 2) + ((kr & 1) << 1);
        int addr = W_OFF + kc * 8192 + (wcs * 4 + gate) * 512
                 + (gs * 4 + tts) * 16 + ng * 8 + pos;
        *(__half*)(smem_c + addr) = __float2half_rn(v);
    }
    if (tid < G_DIM) sb[tid] = b[tid];
    if (tid < H_DIM * 2) sWd[tid] = Wd[tid];

    // convert own cp.async quads: XS -> A buf0 x-region (each thread converts what it fetched)
    CP_WAIT0();
    for (int i = tid; i < ROWS * 23; i += THREADS) {
        int r = i / 23, q = i - r * 23;
        float4 v = *(const float4*)(smem_c + XS_OFF + (r * 23 + q) * 16);
        __half2 h01 = __floats2half2_rn(v.x, v.y);
        __half2 h23 = __floats2half2_rn(v.z, v.w);
        int ad = a_addr(r, 4 * q);
        *(uint*)(smem_c + A_OFF + ad)      = *(uint*)&h01;
        *(uint*)(smem_c + A_OFF + ad + 16) = *(uint*)&h23;
    }
    __syncthreads();

    float c_st[16];
    #pragma unroll
    for (int i = 0; i < 16; ++i) c_st[i] = 0.0f;

    // ---------------- time loop ----------------
    #pragma unroll 1
    for (int t = 0; t < T_LEN; ++t) {
        const char* abr = smem_c + A_OFF + (t & 1) * A_BUFSZ;        // read buffer
        char*       abw = smem_c + A_OFF + ((t & 1) ^ 1) * A_BUFSZ;  // write buffer

        // prefetch x(t+1) -> XS (consumed by this same thread at end of step)
        if (t + 1 < T_LEN) {
            for (int i = tid; i < ROWS * 23; i += THREADS) {
                int r = i / 23, q = i - r * 23;
                cp_async16(sbase + XS_OFF + (r * 23 + q) * 16,
                           x + ((size_t)(row0 + r) * T_LEN + (t + 1)) * F_DIM + q * 4);
            }
            CP_COMMIT();
        }

        // acc[mt][gate*2+ng][4], init = bias
        float acc[2][8][4];
        #pragma unroll
        for (int j = 0; j < 8; ++j) {
            int gate = j >> 1, ng = j & 1;
            int col = gate * 64 + wc * 16 + ng * 8 + 2 * tt;
            float2 bv = *(const float2*)(sb + col);
            #pragma unroll
            for (int mt = 0; mt < 2; ++mt) {
                acc[mt][j][0] = bv.x; acc[mt][j][1] = bv.y;
                acc[mt][j][2] = bv.x; acc[mt][j][3] = bv.y;
            }
        }

        // MMA over 10 K-chunks (reads buffer t&1 only)
        #pragma unroll
        for (int kc = 0; kc < NKC; ++kc) {
            int a0off = (((2 * wr + 0) * NKC + kc) * 32 + lane) << 4;
            int a1off = (((2 * wr + 1) * NKC + kc) * 32 + lane) << 4;
            uint4 a0 = *(const uint4*)(abr + a0off);
            uint4 a1 = *(const uint4*)(abr + a1off);
            const char* wb = smem_c + W_OFF + kc * 8192 + wc * 2048 + (g * 4 + tt) * 16;
            #pragma unroll
            for (int gate = 0; gate < 4; ++gate) {
                uint4 bq = *(const uint4*)(wb + gate * 512);
                mma16816(acc[0][gate * 2 + 0], a0, bq.x, bq.y);
                mma16816(acc[0][gate * 2 + 1], a0, bq.z, bq.w);
                mma16816(acc[1][gate * 2 + 0], a1, bq.x, bq.y);
                mma16816(acc[1][gate * 2 + 1], a1, bq.z, bq.w);
            }
        }
        // NO barrier: epilogue/conversion write the OTHER buffer

        // epilogue: gates -> c,h ; write h(t) (fp16) into write-buffer h-region
        #pragma unroll
        for (int mt = 0; mt < 2; ++mt) {
            int mtg = wr * 2 + mt;
            #pragma unroll
            for (int ng = 0; ng < 2; ++ng) {
                float hv[4];
                #pragma unroll
                for (int s = 0; s < 4; ++s) {
                    int ci = mt * 8 + ng * 4 + s;
                    float ig = sig_ap(acc[mt][0 + ng][s]);
                    float fg = sig_ap(acc[mt][2 + ng][s]);
                    float gg = tanh_ap(acc[mt][4 + ng][s]);
                    float og = sig_ap(acc[mt][6 + ng][s]);
                    float cn = fmaf(fg, c_st[ci], ig * gg);
                    c_st[ci] = cn;
                    hv[s] = og * tanh_ap(cn);
                }
                int k  = 96 + wc * 16 + ng * 8 + 2 * tt;
                int kc = k >> 4, kr = k & 15, tK = (kr >> 1) & 3;
                int base = (((mtg * NKC + kc) * 32 + g * 4 + tK) << 4) + ((kr >> 3) << 3);
                __half2 h01 = __floats2half2_rn(hv[0], hv[1]);   // row g
                __half2 h23 = __floats2half2_rn(hv[2], hv[3]);   // row g+8
                uint2 hq = make_uint2(*(uint*)&h01, *(uint*)&h23);
                *(uint2*)(abw + base) = hq;                      // STS.64
            }
        }

        // convert own quads of x(t+1) -> write-buffer x-region
        if (t + 1 < T_LEN) {
            CP_WAIT0();
            for (int i = tid; i < ROWS * 23; i += THREADS) {
                int r = i / 23, q = i - r * 23;
                float4 v = *(const float4*)(smem_c + XS_OFF + (r * 23 + q) * 16);
                __half2 h01 = __floats2half2_rn(v.x, v.y);
                __half2 h23 = __floats2half2_rn(v.z, v.w);
                int ad = a_addr(r, 4 * q);
                *(uint*)(abw + ad)      = *(uint*)&h01;
                *(uint*)(abw + ad + 16) = *(uint*)&h23;
            }
        }

        __syncthreads();   // write-buffer complete before next step's MMA reads it
    }

    // ---------------- head ----------------
    // T_LEN even: final h(39) lives in buffer 0
    if (tid < ROWS * 2) {
        int r = tid >> 1, l = tid & 1;
        float s = bd[l];
        #pragma unroll
        for (int up = 0; up < 32; ++up) {
            int u = 2 * up;
            uint hb = *(uint*)(smem_c + A_OFF + a_addr(r, 96 + u));
            float2 hf = __half22float2(*(__half2*)&hb);
            s += hf.x * sWd[u * 2 + l] + hf.y * sWd[(u + 1) * 2 + l];
        }
        out[(size_t)(row0 + r) * 2 + l] = sig_acc(s);
    }
}

extern "C" void kernel_launch(void* const* d_in, const int* in_sizes, int n_in,
                              void* d_out, int out_size)
{
    const float* x  = (const float*)d_in[0];
    const float* Wk = (const float*)d_in[1];
    const float* Wr = (const float*)d_in[2];
    const float* b  = (const float*)d_in[3];
    const float* Wd = (const float*)d_in[4];
    const float* bd = (const float*)d_in[5];
    float* out = (float*)d_out;

    cudaFuncSetAttribute(lstm_hmma_kernel,
                         cudaFuncAttributeMaxDynamicSharedMemorySize, SMEM_BYTES);
    lstm_hmma_kernel<<<B_TOT / ROWS, THREADS, SMEM_BYTES>>>(x, Wk, Wr, b, Wd, bd, out);
}

// round 10
// speedup vs baseline: 7.9151x; 1.5238x over previous
#include <cuda_runtime.h>
#include <cuda_fp16.h>
#include <cstdint>

#define B_TOT   32768
#define T_LEN   40
#define F_DIM   92
#define H_DIM   64
#define G_DIM   256
#define ROWS    128
#define THREADS 512
#define KP      160      // k: 0..91 x, 92..95 pad, 96..159 h
#define NKC     10

// ---------------- SMEM byte offsets ----------------
#define W_OFF    0                 // fp16 W: [kc][blk=wc*4+gate][lane]{16B} : 10*16*512 = 81920
#define A_OFF    81920             // fp16 A frags x2 buffers: 2*40960
#define A_BUFSZ  40960
#define XS_OFF   163840            // fp32 x stage, group-linear slots: 4*736*16 = 47104
#define SB_OFF   210944            // bias fp32 [256] = 1024
#define SWD_OFF  211968            // Wd fp32 [64][2] = 512
#define SMEM_BYTES 212480

typedef unsigned int uint;

__device__ __forceinline__ uint32_t smem_u32(const void* p) {
    uint32_t a;
    asm("{ .reg .u64 t; cvta.to.shared.u64 t, %1; cvt.u32.u64 %0, t; }" : "=r"(a) : "l"(p));
    return a;
}
__device__ __forceinline__ void cp_async16(uint32_t dst, const void* src) {
    asm volatile("cp.async.cg.shared.global [%0], [%1], 16;" :: "r"(dst), "l"(src) : "memory");
}
#define CP_COMMIT() asm volatile("cp.async.commit_group;" ::: "memory")
#define CP_WAIT0()  asm volatile("cp.async.wait_group 0;" ::: "memory")

__device__ __forceinline__ void mma16816(float* d, const uint4& a, uint b0, uint b1) {
    asm volatile(
        "mma.sync.aligned.m16n8k16.row.col.f32.f16.f16.f32 "
        "{%0,%1,%2,%3}, {%4,%5,%6,%7}, {%8,%9}, {%0,%1,%2,%3};"
        : "+f"(d[0]), "+f"(d[1]), "+f"(d[2]), "+f"(d[3])
        : "r"(a.x), "r"(a.y), "r"(a.z), "r"(a.w), "r"(b0), "r"(b1));
}

__device__ __forceinline__ float tanh_ap(float x) {
    float r; asm("tanh.approx.f32 %0, %1;" : "=f"(r) : "f"(x)); return r;
}
__device__ __forceinline__ float sig_ap(float x) {
    return fmaf(0.5f, tanh_ap(0.5f * x), 0.5f);
}
__device__ __forceinline__ float sig_acc(float x) { return 1.0f / (1.0f + __expf(-x)); }

// A-plane byte offset for element (row, k) within one buffer; k even pairs contiguous 4B
__device__ __forceinline__ int a_addr(int row, int k) {
    int mtg = row >> 4, r16 = row & 15, g = r16 & 7;
    int kc = k >> 4, kr = k & 15, tK = (kr >> 1) & 3;
    return (((mtg * NKC + kc) * 32 + g * 4 + tK) << 4) + ((kr >> 3) << 3) + ((r16 >> 3) << 2);
}

__global__ void __launch_bounds__(THREADS, 1)
lstm_hmma_kernel(const float* __restrict__ x,
                 const float* __restrict__ Wk,
                 const float* __restrict__ Wr,
                 const float* __restrict__ b,
                 const float* __restrict__ Wd,
                 const float* __restrict__ bd,
                 float* __restrict__ out)
{
    extern __shared__ char smem_c[];
    float* sb  = (float*)(smem_c + SB_OFF);
    float* sWd = (float*)(smem_c + SWD_OFF);
    const uint32_t sbase = smem_u32(smem_c);

    const int tid  = threadIdx.x;
    const int w    = tid >> 5;
    const int lane = tid & 31;
    const int g    = lane >> 2;      // mma group id
    const int tt   = lane & 3;       // thread-in-group
    const int wr   = w >> 2;         // warp row-group (0..3): rows 32*wr..+31
    const int wc   = w & 3;          // warp unit-group (0..3): units 16*wc..+15
    const int row0 = blockIdx.x * ROWS;

    // ---------------- prologue ----------------
    for (int i = tid; i < (2 * A_BUFSZ) / 16; i += THREADS)
        *(uint4*)(smem_c + A_OFF + i * 16) = make_uint4(0, 0, 0, 0);

    // per-thread x-staging tables (group wr owns rows 32wr..+31; 736 quads/group)
    const int ltid = wc * 32 + lane;              // 0..127 within group
    int nv = 736 - ltid * 6;
    nv = nv < 0 ? 0 : (nv > 6 ? 6 : nv);
    uint goffs[6], aoffs[6];
    #pragma unroll
    for (int j = 0; j < 6; ++j) {
        int s  = ltid * 6 + j;
        int rl = s / 23, q = s - rl * 23;
        int r  = wr * 32 + (rl & 31);
        goffs[j] = (uint)((((row0 + r) * T_LEN) * F_DIM + q * 4) * 4);  // bytes, t=0
        aoffs[j] = (uint)a_addr(r, 4 * q);
    }
    const uint32_t xsb = sbase + XS_OFF + (uint)(wr * 736 + ltid * 6) * 16;
    const char*    xsr = smem_c + XS_OFF + (wr * 736 + ltid * 6) * 16;

    // cp.async x(t=0)
    #pragma unroll
    for (int j = 0; j < 6; ++j)
        if (j < nv) cp_async16(xsb + j * 16, (const char*)x + goffs[j]);
    CP_COMMIT();

    // W -> fp16 frag-permuted SMEM (paired-ng layout for LDS.128 B loads)
    for (int idx = tid; idx < KP * G_DIM; idx += THREADS) {
        int n = idx & 255, k = idx >> 8;
        float v;
        if (k < F_DIM)       v = Wk[k * G_DIM + n];
        else if (k < 96)     v = 0.0f;
        else                 v = Wr[(k - 96) * G_DIM + n];
        int kc = k >> 4, kr = k & 15;
        int gate = n >> 6, wcs = (n >> 4) & 3, ng = (n >> 3) & 1, gs = n & 7;
        int tts = (kr >> 1) & 3;
        int pos = ((kr >> 3) << 2) + ((kr & 1) << 1);
        int addr = W_OFF + kc * 8192 + (wcs * 4 + gate) * 512
                 + (gs * 4 + tts) * 16 + ng * 8 + pos;
        *(__half*)(smem_c + addr) = __float2half_rn(v);
    }
    if (tid < G_DIM) sb[tid] = b[tid];
    if (tid < H_DIM * 2) sWd[tid] = Wd[tid];

    // convert own quads: XS -> A buf0 x-region
    CP_WAIT0();
    #pragma unroll
    for (int j = 0; j < 6; ++j) {
        if (j < nv) {
            float4 v = *(const float4*)(xsr + j * 16);
            __half2 h01 = __floats2half2_rn(v.x, v.y);
            __half2 h23 = __floats2half2_rn(v.z, v.w);
            *(uint*)(smem_c + A_OFF + aoffs[j])      = *(uint*)&h01;
            *(uint*)(smem_c + A_OFF + aoffs[j] + 16) = *(uint*)&h23;
        }
    }
    __syncthreads();

    float c_st[16];
    #pragma unroll
    for (int i = 0; i < 16; ++i) c_st[i] = 0.0f;

    // ---------------- time loop ----------------
    #pragma unroll 1
    for (int t = 0; t < T_LEN; ++t) {
        const char* abr = smem_c + A_OFF + (t & 1) * A_BUFSZ;
        char*       abw = smem_c + A_OFF + ((t & 1) ^ 1) * A_BUFSZ;

        // prefetch x(t+1) (precomputed addresses; +368 B per step)
        if (t + 1 < T_LEN) {
            const char* xb = (const char*)x + (size_t)(t + 1) * (F_DIM * 4);
            #pragma unroll
            for (int j = 0; j < 6; ++j)
                if (j < nv) cp_async16(xsb + j * 16, xb + goffs[j]);
            CP_COMMIT();
        }

        // acc[mt][gate*2+ng][4], init = bias
        float acc[2][8][4];
        #pragma unroll
        for (int j = 0; j < 8; ++j) {
            int gate = j >> 1, ng = j & 1;
            int col = gate * 64 + wc * 16 + ng * 8 + 2 * tt;
            float2 bv = *(const float2*)(sb + col);
            #pragma unroll
            for (int mt = 0; mt < 2; ++mt) {
                acc[mt][j][0] = bv.x; acc[mt][j][1] = bv.y;
                acc[mt][j][2] = bv.x; acc[mt][j][3] = bv.y;
            }
        }

        // MMA over 10 K-chunks (reads buffer t&1, rows 32wr..+31 only)
        #pragma unroll
        for (int kc = 0; kc < NKC; ++kc) {
            int a0off = (((2 * wr + 0) * NKC + kc) * 32 + lane) << 4;
            int a1off = (((2 * wr + 1) * NKC + kc) * 32 + lane) << 4;
            uint4 a0 = *(const uint4*)(abr + a0off);
            uint4 a1 = *(const uint4*)(abr + a1off);
            const char* wb = smem_c + W_OFF + kc * 8192 + wc * 2048 + (g * 4 + tt) * 16;
            #pragma unroll
            for (int gate = 0; gate < 4; ++gate) {
                uint4 bq = *(const uint4*)(wb + gate * 512);
                mma16816(acc[0][gate * 2 + 0], a0, bq.x, bq.y);
                mma16816(acc[0][gate * 2 + 1], a0, bq.z, bq.w);
                mma16816(acc[1][gate * 2 + 0], a1, bq.x, bq.y);
                mma16816(acc[1][gate * 2 + 1], a1, bq.z, bq.w);
            }
        }

        // epilogue: gates -> c,h ; write h(t) into write-buffer (own rows only)
        #pragma unroll
        for (int mt = 0; mt < 2; ++mt) {
            int mtg = wr * 2 + mt;
            #pragma unroll
            for (int ng = 0; ng < 2; ++ng) {
                float hv[4];
                #pragma unroll
                for (int s = 0; s < 4; ++s) {
                    int ci = mt * 8 + ng * 4 + s;
                    float ig = sig_ap(acc[mt][0 + ng][s]);
                    float fg = sig_ap(acc[mt][2 + ng][s]);
                    float gg = tanh_ap(acc[mt][4 + ng][s]);
                    float og = sig_ap(acc[mt][6 + ng][s]);
                    float cn = fmaf(fg, c_st[ci], ig * gg);
                    c_st[ci] = cn;
                    hv[s] = og * tanh_ap(cn);
                }
                int k  = 96 + wc * 16 + ng * 8 + 2 * tt;
                int kc = k >> 4, kr = k & 15, tK = (kr >> 1) & 3;
                int base = (((mtg * NKC + kc) * 32 + g * 4 + tK) << 4) + ((kr >> 3) << 3);
                __half2 h01 = __floats2half2_rn(hv[0], hv[1]);   // row g
                __half2 h23 = __floats2half2_rn(hv[2], hv[3]);   // row g+8
                uint2 hq = make_uint2(*(uint*)&h01, *(uint*)&h23);
                *(uint2*)(abw + base) = hq;                      // STS.64
            }
        }

        // convert own quads of x(t+1) -> write-buffer x-region (own rows only)
        if (t + 1 < T_LEN) {
            CP_WAIT0();
            #pragma unroll
            for (int j = 0; j < 6; ++j) {
                if (j < nv) {
                    float4 v = *(const float4*)(xsr + j * 16);
                    __half2 h01 = __floats2half2_rn(v.x, v.y);
                    __half2 h23 = __floats2half2_rn(v.z, v.w);
                    *(uint*)(abw + aoffs[j])      = *(uint*)&h01;
                    *(uint*)(abw + aoffs[j] + 16) = *(uint*)&h23;
                }
            }
        }

        // group-local barrier: only the 4 warps sharing rows 32wr..+31 must sync
        asm volatile("bar.sync %0, 128;" :: "r"(wr + 1) : "memory");
    }

    // ---------------- head ----------------
    __syncthreads();   // cross-group visibility of final h (buffer 0, T_LEN even)
    if (tid < ROWS * 2) {
        int r = tid >> 1, l = tid & 1;
        float s = bd[l];
        #pragma unroll
        for (int up = 0; up < 32; ++up) {
            int u = 2 * up;
            uint hb = *(uint*)(smem_c + A_OFF + a_addr(r, 96 + u));
            float2 hf = __half22float2(*(__half2*)&hb);
            s += hf.x * sWd[u * 2 + l] + hf.y * sWd[(u + 1) * 2 + l];
        }
        out[(size_t)(row0 + r) * 2 + l] = sig_acc(s);
    }
}

extern "C" void kernel_launch(void* const* d_in, const int* in_sizes, int n_in,
                              void* d_out, int out_size)
{
    const float* x  = (const float*)d_in[0];
    const float* Wk = (const float*)d_in[1];
    const float* Wr = (const float*)d_in[2];
    const float* b  = (const float*)d_in[3];
    const float* Wd = (const float*)d_in[4];
    const float* bd = (const float*)d_in[5];
    float* out = (float*)d_out;

    cudaFuncSetAttribute(lstm_hmma_kernel,
                         cudaFuncAttributeMaxDynamicSharedMemorySize, SMEM_BYTES);
    lstm_hmma_kernel<<<B_TOT / ROWS, THREADS, SMEM_BYTES>>>(x, Wk, Wr, b, Wd, bd, out);
}

// round 11
// speedup vs baseline: 8.1297x; 1.0271x over previous
#include <cuda_runtime.h>
#include <cuda_fp16.h>
#include <cstdint>

#define B_TOT   32768
#define T_LEN   40
#define F_DIM   92
#define H_DIM   64
#define G_DIM   256
#define ROWS    128
#define THREADS 512
#define KP      160      // k: 0..91 x, 92..95 pad, 96..159 h
#define NKC     10

// ---------------- SMEM byte offsets ----------------
#define W_OFF    0                 // fp16 W: [kc][blk=wc*4+gate][lane]{16B} : 10*16*512 = 81920
#define A_OFF    81920             // fp16 A frags x2 buffers: 2*40960
#define A_BUFSZ  40960
#define XS_OFF   163840            // fp32 x stage, group-linear slots: 4*736*16 = 47104
#define SB_OFF   210944            // bias fp32 [256] = 1024
#define SWD_OFF  211968            // Wd fp32 [64][2] = 512
#define SMEM_BYTES 212480

typedef unsigned int uint;

__device__ __forceinline__ uint32_t smem_u32(const void* p) {
    uint32_t a;
    asm("{ .reg .u64 t; cvta.to.shared.u64 t, %1; cvt.u32.u64 %0, t; }" : "=r"(a) : "l"(p));
    return a;
}
__device__ __forceinline__ void cp_async16(uint32_t dst, const void* src) {
    asm volatile("cp.async.cg.shared.global [%0], [%1], 16;" :: "r"(dst), "l"(src) : "memory");
}
#define CP_COMMIT() asm volatile("cp.async.commit_group;" ::: "memory")
#define CP_WAIT0()  asm volatile("cp.async.wait_group 0;" ::: "memory")

__device__ __forceinline__ void mma16816(float* d, const uint4& a, uint b0, uint b1) {
    asm volatile(
        "mma.sync.aligned.m16n8k16.row.col.f32.f16.f16.f32 "
        "{%0,%1,%2,%3}, {%4,%5,%6,%7}, {%8,%9}, {%0,%1,%2,%3};"
        : "+f"(d[0]), "+f"(d[1]), "+f"(d[2]), "+f"(d[3])
        : "r"(a.x), "r"(a.y), "r"(a.z), "r"(a.w), "r"(b0), "r"(b1));
}

// ---- f16x2 activation helpers ----
__device__ __forceinline__ uint htanh2u(uint x) {
    uint r; asm("tanh.approx.f16x2 %0, %1;" : "=r"(r) : "r"(x)); return r;
}
__device__ __forceinline__ uint pack_h2(float a, float b) {
    __half2 t = __floats2half2_rn(a, b);
    return *(uint*)&t;
}
// sigmoid(z0),sigmoid(z1) as half2: 0.5*tanh(0.5 z)+0.5
__device__ __forceinline__ uint sig2u(float z0, float z1) {
    uint th = htanh2u(pack_h2(0.5f * z0, 0.5f * z1));
    __half2 t = *(__half2*)&th;
    const __half2 h05 = __floats2half2_rn(0.5f, 0.5f);
    __half2 r = __hfma2(t, h05, h05);
    return *(uint*)&r;
}
__device__ __forceinline__ float2 h2f2(uint h) { return __half22float2(*(__half2*)&h); }

__device__ __forceinline__ float sig_acc(float x) { return 1.0f / (1.0f + __expf(-x)); }

// A-plane byte offset for element (row, k) within one buffer; k even pairs contiguous 4B
__device__ __forceinline__ int a_addr(int row, int k) {
    int mtg = row >> 4, r16 = row & 15, g = r16 & 7;
    int kc = k >> 4, kr = k & 15, tK = (kr >> 1) & 3;
    return (((mtg * NKC + kc) * 32 + g * 4 + tK) << 4) + ((kr >> 3) << 3) + ((r16 >> 3) << 2);
}

__global__ void __launch_bounds__(THREADS, 1)
lstm_hmma_kernel(const float* __restrict__ x,
                 const float* __restrict__ Wk,
                 const float* __restrict__ Wr,
                 const float* __restrict__ b,
                 const float* __restrict__ Wd,
                 const float* __restrict__ bd,
                 float* __restrict__ out)
{
    extern __shared__ char smem_c[];
    float* sb  = (float*)(smem_c + SB_OFF);
    float* sWd = (float*)(smem_c + SWD_OFF);
    const uint32_t sbase = smem_u32(smem_c);

    const int tid  = threadIdx.x;
    const int w    = tid >> 5;
    const int lane = tid & 31;
    const int g    = lane >> 2;      // mma group id
    const int tt   = lane & 3;       // thread-in-group
    const int wr   = w >> 2;         // warp row-group (0..3): rows 32*wr..+31
    const int wc   = w & 3;          // warp unit-group (0..3): units 16*wc..+15
    const int row0 = blockIdx.x * ROWS;

    // ---------------- prologue ----------------
    for (int i = tid; i < (2 * A_BUFSZ) / 16; i += THREADS)
        *(uint4*)(smem_c + A_OFF + i * 16) = make_uint4(0, 0, 0, 0);

    // per-thread x-staging tables (group wr owns rows 32wr..+31; 736 quads/group)
    const int ltid = wc * 32 + lane;              // 0..127 within group
    int nv = 736 - ltid * 6;
    nv = nv < 0 ? 0 : (nv > 6 ? 6 : nv);
    uint goffs[6], aoffs[6];
    #pragma unroll
    for (int j = 0; j < 6; ++j) {
        int s  = ltid * 6 + j;
        int rl = s / 23, q = s - rl * 23;
        int r  = wr * 32 + (rl & 31);
        goffs[j] = (uint)((((row0 + r) * T_LEN) * F_DIM + q * 4) * 4);  // bytes, t=0
        aoffs[j] = (uint)a_addr(r, 4 * q);
    }
    const uint32_t xsb = sbase + XS_OFF + (uint)(wr * 736 + ltid * 6) * 16;
    const char*    xsr = smem_c + XS_OFF + (wr * 736 + ltid * 6) * 16;

    // cp.async x(t=0)
    #pragma unroll
    for (int j = 0; j < 6; ++j)
        if (j < nv) cp_async16(xsb + j * 16, (const char*)x + goffs[j]);
    CP_COMMIT();

    // W -> fp16 frag-permuted SMEM (paired-ng layout for LDS.128 B loads)
    for (int idx = tid; idx < KP * G_DIM; idx += THREADS) {
        int n = idx & 255, k = idx >> 8;
        float v;
        if (k < F_DIM)       v = Wk[k * G_DIM + n];
        else if (k < 96)     v = 0.0f;
        else                 v = Wr[(k - 96) * G_DIM + n];
        int kc = k >> 4, kr = k & 15;
        int gate = n >> 6, wcs = (n >> 4) & 3, ng = (n >> 3) & 1, gs = n & 7;
        int tts = (kr >> 1) & 3;
        int pos = ((kr >> 3) << 2) + ((kr & 1) << 1);
        int addr = W_OFF + kc * 8192 + (wcs * 4 + gate) * 512
                 + (gs * 4 + tts) * 16 + ng * 8 + pos;
        *(__half*)(smem_c + addr) = __float2half_rn(v);
    }
    if (tid < G_DIM) sb[tid] = b[tid];
    if (tid < H_DIM * 2) sWd[tid] = Wd[tid];

    // convert own quads: XS -> A buf0 x-region
    CP_WAIT0();
    #pragma unroll
    for (int j = 0; j < 6; ++j) {
        if (j < nv) {
            float4 v = *(const float4*)(xsr + j * 16);
            uint h01 = pack_h2(v.x, v.y);
            uint h23 = pack_h2(v.z, v.w);
            *(uint*)(smem_c + A_OFF + aoffs[j])      = h01;
            *(uint*)(smem_c + A_OFF + aoffs[j] + 16) = h23;
        }
    }
    __syncthreads();

    float c_st[16];
    #pragma unroll
    for (int i = 0; i < 16; ++i) c_st[i] = 0.0f;

    // ---------------- time loop ----------------
    #pragma unroll 1
    for (int t = 0; t < T_LEN; ++t) {
        const char* abr = smem_c + A_OFF + (t & 1) * A_BUFSZ;
        char*       abw = smem_c + A_OFF + ((t & 1) ^ 1) * A_BUFSZ;

        // prefetch x(t+1) (precomputed addresses; +368 B per step)
        if (t + 1 < T_LEN) {
            const char* xb = (const char*)x + (size_t)(t + 1) * (F_DIM * 4);
            #pragma unroll
            for (int j = 0; j < 6; ++j)
                if (j < nv) cp_async16(xsb + j * 16, xb + goffs[j]);
            CP_COMMIT();
        }

        // acc[mt][gate*2+ng][4], init = bias
        float acc[2][8][4];
        #pragma unroll
        for (int j = 0; j < 8; ++j) {
            int gate = j >> 1, ng = j & 1;
            int col = gate * 64 + wc * 16 + ng * 8 + 2 * tt;
            float2 bv = *(const float2*)(sb + col);
            #pragma unroll
            for (int mt = 0; mt < 2; ++mt) {
                acc[mt][j][0] = bv.x; acc[mt][j][1] = bv.y;
                acc[mt][j][2] = bv.x; acc[mt][j][3] = bv.y;
            }
        }

        // MMA over 10 K-chunks (reads buffer t&1, rows 32wr..+31 only)
        #pragma unroll
        for (int kc = 0; kc < NKC; ++kc) {
            int a0off = (((2 * wr + 0) * NKC + kc) * 32 + lane) << 4;
            int a1off = (((2 * wr + 1) * NKC + kc) * 32 + lane) << 4;
            uint4 a0 = *(const uint4*)(abr + a0off);
            uint4 a1 = *(const uint4*)(abr + a1off);
            const char* wb = smem_c + W_OFF + kc * 8192 + wc * 2048 + (g * 4 + tt) * 16;
            #pragma unroll
            for (int gate = 0; gate < 4; ++gate) {
                uint4 bq = *(const uint4*)(wb + gate * 512);
                mma16816(acc[0][gate * 2 + 0], a0, bq.x, bq.y);
                mma16816(acc[0][gate * 2 + 1], a0, bq.z, bq.w);
                mma16816(acc[1][gate * 2 + 0], a1, bq.x, bq.y);
                mma16816(acc[1][gate * 2 + 1], a1, bq.z, bq.w);
            }
        }

        // epilogue (f16x2 gates, fp32 c-state): gates -> c,h ; write h(t)
        #pragma unroll
        for (int mt = 0; mt < 2; ++mt) {
            int mtg = wr * 2 + mt;
            #pragma unroll
            for (int ng = 0; ng < 2; ++ng) {
                uint hout[2];
                #pragma unroll
                for (int p = 0; p < 2; ++p) {
                    int s0 = 2 * p, s1 = 2 * p + 1;
                    uint i2 = sig2u(acc[mt][0 + ng][s0], acc[mt][0 + ng][s1]);
                    uint f2 = sig2u(acc[mt][2 + ng][s0], acc[mt][2 + ng][s1]);
                    uint g2 = htanh2u(pack_h2(acc[mt][4 + ng][s0], acc[mt][4 + ng][s1]));
                    uint o2 = sig2u(acc[mt][6 + ng][s0], acc[mt][6 + ng][s1]);
                    float2 fi = h2f2(i2), ff = h2f2(f2), fg = h2f2(g2);
                    int ci = mt * 8 + ng * 4 + s0;
                    float cn0 = fmaf(ff.x, c_st[ci],     fi.x * fg.x);
                    float cn1 = fmaf(ff.y, c_st[ci + 1], fi.y * fg.y);
                    c_st[ci] = cn0; c_st[ci + 1] = cn1;
                    uint t2 = htanh2u(pack_h2(cn0, cn1));
                    __half2 hr = __hmul2(*(__half2*)&o2, *(__half2*)&t2);
                    hout[p] = *(uint*)&hr;
                }
                int k  = 96 + wc * 16 + ng * 8 + 2 * tt;
                int kc = k >> 4, kr = k & 15, tK = (kr >> 1) & 3;
                int base = (((mtg * NKC + kc) * 32 + g * 4 + tK) << 4) + ((kr >> 3) << 3);
                uint2 hq = make_uint2(hout[0], hout[1]);   // rows g, g+8
                *(uint2*)(abw + base) = hq;                // STS.64
            }
        }

        // convert own quads of x(t+1) -> write-buffer x-region (own rows only)
        if (t + 1 < T_LEN) {
            CP_WAIT0();
            #pragma unroll
            for (int j = 0; j < 6; ++j) {
                if (j < nv) {
                    float4 v = *(const float4*)(xsr + j * 16);
                    uint h01 = pack_h2(v.x, v.y);
                    uint h23 = pack_h2(v.z, v.w);
                    *(uint*)(abw + aoffs[j])      = h01;
                    *(uint*)(abw + aoffs[j] + 16) = h23;
                }
            }
        }

        // group-local barrier: only the 4 warps sharing rows 32wr..+31 must sync
        asm volatile("bar.sync %0, 128;" :: "r"(wr + 1) : "memory");
    }

    // ---------------- head ----------------
    __syncthreads();   // cross-group visibility of final h (buffer 0, T_LEN even)
    if (tid < ROWS * 2) {
        int r = tid >> 1, l = tid & 1;
        float s = bd[l];
        #pragma unroll
        for (int up = 0; up < 32; ++up) {
            int u = 2 * up;
            uint hb = *(uint*)(smem_c + A_OFF + a_addr(r, 96 + u));
            float2 hf = __half22float2(*(__half2*)&hb);
            s += hf.x * sWd[u * 2 + l] + hf.y * sWd[(u + 1) * 2 + l];
        }
        out[(size_t)(row0 + r) * 2 + l] = sig_acc(s);
    }
}

extern "C" void kernel_launch(void* const* d_in, const int* in_sizes, int n_in,
                              void* d_out, int out_size)
{
    const float* x  = (const float*)d_in[0];
    const float* Wk = (const float*)d_in[1];
    const float* Wr = (const float*)d_in[2];
    const float* b  = (const float*)d_in[3];
    const float* Wd = (const float*)d_in[4];
    const float* bd = (const float*)d_in[5];
    float* out = (float*)d_out;

    cudaFuncSetAttribute(lstm_hmma_kernel,
                         cudaFuncAttributeMaxDynamicSharedMemorySize, SMEM_BYTES);
    lstm_hmma_kernel<<<B_TOT / ROWS, THREADS, SMEM_BYTES>>>(x, Wk, Wr, b, Wd, bd, out);
}